// round 14
// baseline (speedup 1.0000x reference)
#include <cuda_runtime.h>
#include <cuda_fp16.h>
#include <math.h>

#define NHH   4
#define HDD   64
#define KDD   16
#define DDD   64
#define NNN   1600
#define BBB   16
#define HIMG  40
#define WIMG  40
#define DIMC  256
#define EPSB  1e-5f
#define SCALEQ 0.25f
#define L2E   1.4426950408889634f

// ---------------- device scratch ----------------
__device__ float    g_conv[BBB*DIMC*NNN];
__device__ __half   g_qh [BBB*NNN*KDD];
__device__ __half   g_kh [BBB*NNN*KDD];
__device__ __half   g_vT [BBB*DDD*NNN];
__device__ float    g_prev[BBB*HDD*NNN];
__device__ __half   g_cath[BBB*NNN*DIMC];
__device__ float    g_dw_wf[NHH*HDD*25];
__device__ float    g_dw_bf[NHH*HDD];
__device__ __half   g_qkv_wh[NHH*96*HDD];
__device__ float    g_qkv_bf[NHH*96];
__device__ __half   g_p_wh[DIMC*DIMC];
__device__ float    g_p_bf[DIMC];
__device__ unsigned g_kmaxu[NHH*BBB];
__device__ float    g_bmax[NHH];

// ---------------- helpers ----------------
__device__ __forceinline__ float ex2(float x) {
    float r; asm("ex2.approx.f32 %0, %1;" : "=f"(r) : "f"(x)); return r;
}
__device__ __forceinline__ unsigned packh2(float a, float b) {
    __half2 h = __floats2half2_rn(a, b);
    return *(unsigned*)&h;
}
__device__ __forceinline__ void mma_f16(float c[4], const unsigned a[4],
                                        unsigned b0, unsigned b1) {
    asm volatile("mma.sync.aligned.m16n8k16.row.col.f32.f16.f16.f32 "
        "{%0,%1,%2,%3}, {%4,%5,%6,%7}, {%8,%9}, {%0,%1,%2,%3};"
        : "+f"(c[0]), "+f"(c[1]), "+f"(c[2]), "+f"(c[3])
        : "r"(a[0]), "r"(a[1]), "r"(a[2]), "r"(a[3]), "r"(b0), "r"(b1));
}
__device__ __forceinline__ void ldsm4(unsigned& r0, unsigned& r1, unsigned& r2, unsigned& r3,
                                      unsigned addr) {
    asm volatile("ldmatrix.sync.aligned.m8n8.x4.shared.b16 {%0,%1,%2,%3}, [%4];"
        : "=r"(r0), "=r"(r1), "=r"(r2), "=r"(r3) : "r"(addr));
}
__device__ __forceinline__ void cp16(void* dst, const void* src) {
    unsigned d = (unsigned)__cvta_generic_to_shared(dst);
    asm volatile("cp.async.cg.shared.global [%0], [%1], 16;" :: "r"(d), "l"(src));
}
#define CP_COMMIT asm volatile("cp.async.commit_group;" ::: "memory")
#define CP_WAIT1  asm volatile("cp.async.wait_group 1;"  ::: "memory")
#define CP_WAIT0  asm volatile("cp.async.wait_group 0;"  ::: "memory")

// ---------------- fold BN into weights + bias-max + kmax reset ----------------
__global__ void prep_fold(
    const float* dw_w, const float* dw_g, const float* dw_b, const float* dw_m, const float* dw_v,
    const float* q_w,  const float* q_g,  const float* q_b,  const float* q_m,  const float* q_v,
    const float* k_w,  const float* k_g,  const float* k_b,  const float* k_m,  const float* k_v,
    const float* v_w,  const float* v_g,  const float* v_b,  const float* v_m,  const float* v_v,
    const float* p_w,  const float* p_g,  const float* p_b,  const float* p_m,  const float* p_v,
    const float* attn_bias)
{
    int t = blockIdx.x * blockDim.x + threadIdx.x;
    int stride = gridDim.x * blockDim.x;

    for (int idx = t; idx < NHH*HDD*25; idx += stride) {
        int ch = idx / 25;
        float s = dw_g[ch] * rsqrtf(dw_v[ch] + EPSB);
        g_dw_wf[idx] = dw_w[idx] * s;
    }
    for (int ch = t; ch < NHH*HDD; ch += stride) {
        float s = dw_g[ch] * rsqrtf(dw_v[ch] + EPSB);
        g_dw_bf[ch] = dw_b[ch] - s * dw_m[ch];
    }
    for (int idx = t; idx < NHH*96*HDD; idx += stride) {
        int r = idx / HDD, c = idx % HDD;
        int i = r / 96, oc = r % 96;
        float s; const float* w;
        if (oc < 16) {
            int j = i*KDD + oc;
            s = q_g[j] * rsqrtf(q_v[j] + EPSB) * (SCALEQ * L2E);
            w = q_w + (size_t)j * HDD;
        } else if (oc < 32) {
            int j = i*KDD + (oc - 16);
            s = k_g[j] * rsqrtf(k_v[j] + EPSB);
            w = k_w + (size_t)j * HDD;
        } else {
            int j = i*DDD + (oc - 32);
            s = v_g[j] * rsqrtf(v_v[j] + EPSB);
            w = v_w + (size_t)j * HDD;
        }
        g_qkv_wh[idx] = __float2half_rn(w[c] * s);
    }
    for (int r = t; r < NHH*96; r += stride) {
        int i = r / 96, oc = r % 96;
        float s, bias;
        if (oc < 16) {
            int j = i*KDD + oc;
            s = q_g[j] * rsqrtf(q_v[j] + EPSB);
            bias = (q_b[j] - s * q_m[j]) * (SCALEQ * L2E);
        } else if (oc < 32) {
            int j = i*KDD + (oc - 16);
            s = k_g[j] * rsqrtf(k_v[j] + EPSB);
            bias = k_b[j] - s * k_m[j];
        } else {
            int j = i*DDD + (oc - 32);
            s = v_g[j] * rsqrtf(v_v[j] + EPSB);
            bias = v_b[j] - s * v_m[j];
        }
        g_qkv_bf[r] = bias;
    }
    for (int idx = t; idx < DIMC*DIMC; idx += stride) {
        int o = idx / DIMC;
        float s = p_g[o] * rsqrtf(p_v[o] + EPSB);
        g_p_wh[idx] = __float2half_rn(p_w[idx] * s);
    }
    for (int o = t; o < DIMC; o += stride) {
        float s = p_g[o] * rsqrtf(p_v[o] + EPSB);
        g_p_bf[o] = p_b[o] - s * p_m[o];
    }

    if (blockIdx.x == 0) {
        int tt = threadIdx.x;
        if (tt < NHH*BBB) g_kmaxu[tt] = 0u;
        int wrp = tt >> 5, ln = tt & 31;
        if (wrp < NHH) {
            float mx = -1e30f;
            for (int n = ln; n < NNN; n += 32)
                mx = fmaxf(mx, attn_bias[wrp*NNN + n]);
            #pragma unroll
            for (int msk = 16; msk; msk >>= 1)
                mx = fmaxf(mx, __shfl_xor_sync(0xffffffffu, mx, msk));
            if (ln == 0) g_bmax[wrp] = mx * L2E;
        }
    }
}

// ---------------- depthwise 5x5 conv, 4 outputs/thread ----------------
__global__ __launch_bounds__(256) void dwconv_all(const float* __restrict__ x)
{
    int idx = blockIdx.x * 256 + threadIdx.x;
    int n4 = idx % 400;
    int c  = (idx / 400) % DIMC;
    int b  = idx / (400 * DIMC);
    int h  = n4 / 10, w0 = (n4 % 10) * 4;

    const float* xin = x + ((size_t)b * DIMC + c) * NNN;
    const float* wf  = g_dw_wf + c * 25;
    float bias = g_dw_bf[c];
    float a0 = bias, a1 = bias, a2 = bias, a3 = bias;

    #pragma unroll
    for (int dy = 0; dy < 5; dy++) {
        int hh = h + dy - 2;
        if ((unsigned)hh >= (unsigned)HIMG) continue;
        const float* row = xin + hh*WIMG;
        float v[8];
        #pragma unroll
        for (int j = 0; j < 8; j++) {
            int ww = w0 - 2 + j;
            v[j] = ((unsigned)ww < (unsigned)WIMG) ? row[ww] : 0.f;
        }
        #pragma unroll
        for (int dx = 0; dx < 5; dx++) {
            float wt = wf[dy*5 + dx];
            a0 += wt*v[dx];   a1 += wt*v[dx+1];
            a2 += wt*v[dx+2]; a3 += wt*v[dx+3];
        }
    }
    *(float4*)&g_conv[((size_t)b*DIMC + c)*NNN + h*WIMG + w0] = make_float4(a0, a1, a2, a3);
}

// ---------------- QKV projection via fp16 MMA (+ fused prev add + k-norm max) ----------------
__global__ __launch_bounds__(256) void qkv_mma(int head, int addprev)
{
    __shared__ __align__(16) __half wsh[96*72];
    __shared__ __align__(16) __half xsh[64*72];

    int b  = blockIdx.x / 25;
    int p0 = (blockIdx.x % 25) * 64;
    int t  = threadIdx.x;
    int wp   = t >> 5;
    int lane = t & 31;
    int g    = lane >> 2;
    int qd   = lane & 3;

    for (int i = t; i < 768; i += 256) {
        int row = i >> 3, c8 = (i & 7) * 8;
        cp16(&wsh[row*72 + c8], &g_qkv_wh[(size_t)head*96*64 + row*64 + c8]);
    }
    CP_COMMIT;

    {
        int c  = t >> 2;
        int i4 = t & 3;
        int cX = c ^ (i4 << 3);
        const float* cb = g_conv + ((size_t)b*DIMC + head*HDD + c)*NNN + p0 + i4*16;
        const float* pb = g_prev + ((size_t)b*HDD + c)*NNN + p0 + i4*16;
        #pragma unroll
        for (int j4 = 0; j4 < 4; j4++) {
            float4 f = *(const float4*)&cb[j4*4];
            if (addprev) {
                float4 pv = *(const float4*)&pb[j4*4];
                f.x += pv.x; f.y += pv.y; f.z += pv.z; f.w += pv.w;
            }
            int pbase = i4*16 + j4*4;
            xsh[(pbase + 0)*72 + cX] = __float2half_rn(f.x);
            xsh[(pbase + 1)*72 + cX] = __float2half_rn(f.y);
            xsh[(pbase + 2)*72 + cX] = __float2half_rn(f.z);
            xsh[(pbase + 3)*72 + cX] = __float2half_rn(f.w);
        }
    }
    CP_WAIT0;
    __syncthreads();

    int n0 = wp * 8;
    int cXor = ((wp >> 1) & 3) << 3;
    float acc[6][4];
    #pragma unroll
    for (int mt = 0; mt < 6; mt++)
        #pragma unroll
        for (int j = 0; j < 4; j++) acc[mt][j] = 0.f;

    #pragma unroll
    for (int ks = 0; ks < 4; ks++) {
        unsigned b0 = *(const unsigned*)&xsh[(n0 + g)*72 + ((ks*16 + 2*qd    ) ^ cXor)];
        unsigned b1 = *(const unsigned*)&xsh[(n0 + g)*72 + ((ks*16 + 2*qd + 8) ^ cXor)];
        #pragma unroll
        for (int mt = 0; mt < 6; mt++) {
            unsigned a[4];
            a[0] = *(const unsigned*)&wsh[(mt*16 + g    )*72 + ks*16 + 2*qd];
            a[1] = *(const unsigned*)&wsh[(mt*16 + g + 8)*72 + ks*16 + 2*qd];
            a[2] = *(const unsigned*)&wsh[(mt*16 + g    )*72 + ks*16 + 2*qd + 8];
            a[3] = *(const unsigned*)&wsh[(mt*16 + g + 8)*72 + ks*16 + 2*qd + 8];
            mma_f16(acc[mt], a, b0, b1);
        }
    }

    float kn0 = 0.f, kn1 = 0.f;
    int n = p0 + n0 + 2*qd;
    #pragma unroll
    for (int mt = 0; mt < 6; mt++) {
        int oc0 = mt*16 + g, oc1 = oc0 + 8;
        float bb0 = g_qkv_bf[head*96 + oc0];
        float bb1 = g_qkv_bf[head*96 + oc1];
        float v00 = acc[mt][0] + bb0, v01 = acc[mt][1] + bb0;
        float v10 = acc[mt][2] + bb1, v11 = acc[mt][3] + bb1;
        if (mt == 0) {
            g_qh[((size_t)b*NNN + n    )*KDD + oc0] = __float2half_rn(v00);
            g_qh[((size_t)b*NNN + n + 1)*KDD + oc0] = __float2half_rn(v01);
            g_qh[((size_t)b*NNN + n    )*KDD + oc1] = __float2half_rn(v10);
            g_qh[((size_t)b*NNN + n + 1)*KDD + oc1] = __float2half_rn(v11);
        } else if (mt == 1) {
            int k0 = oc0 - 16, k1 = oc1 - 16;
            g_kh[((size_t)b*NNN + n    )*KDD + k0] = __float2half_rn(v00);
            g_kh[((size_t)b*NNN + n + 1)*KDD + k0] = __float2half_rn(v01);
            g_kh[((size_t)b*NNN + n    )*KDD + k1] = __float2half_rn(v10);
            g_kh[((size_t)b*NNN + n + 1)*KDD + k1] = __float2half_rn(v11);
            kn0 = v00*v00 + v10*v10;
            kn1 = v01*v01 + v11*v11;
        } else {
            int d0 = oc0 - 32, d1 = oc1 - 32;
            *(__half2*)&g_vT[((size_t)b*DDD + d0)*NNN + n] = __floats2half2_rn(v00, v01);
            *(__half2*)&g_vT[((size_t)b*DDD + d1)*NNN + n] = __floats2half2_rn(v10, v11);
        }
    }

    #pragma unroll
    for (int msk = 4; msk <= 16; msk <<= 1) {
        kn0 += __shfl_xor_sync(0xffffffffu, kn0, msk);
        kn1 += __shfl_xor_sync(0xffffffffu, kn1, msk);
    }
    float kmx = fmaxf(kn0, kn1);
    kmx = fmaxf(kmx, __shfl_xor_sync(0xffffffffu, kmx, 1));
    kmx = fmaxf(kmx, __shfl_xor_sync(0xffffffffu, kmx, 2));
    if (lane == 0)
        atomicMax(&g_kmaxu[head*BBB + b], __float_as_uint(kmx));
}

// ---------------- fp16 MMA flash attention: 3-deep rings, lean regs, 4 blocks/SM ----------------
#define KSTRH 24
#define VSTRH 72
#define KBYTES (64*KSTRH*2)    // 3072
#define VBYTES (64*VSTRH*2)    // 9216
#define ONE2  0x3C003C00u

__global__ __launch_bounds__(128, 4) void attn_mma(const float* __restrict__ attn_bias, int head)
{
    __shared__ __align__(16) __half ksm[3][64*KSTRH];    //  9216 B
    __shared__ __align__(16) __half vsm[3][64*VSTRH];    // 27648 B
    __shared__ __align__(16) float  bism[3][64];         //   768 B

    int b  = blockIdx.x / 25;
    int q0 = (blockIdx.x % 25) * 64;
    int t    = threadIdx.x;
    int w    = t >> 5;
    int lane = t & 31;
    int g    = lane >> 2;
    int qd   = lane & 3;
    int mi   = lane >> 3;
    int mr   = lane & 7;

    const __half* kbase = g_kh + (size_t)b*NNN*KDD;
    const __half* vbase = g_vT + (size_t)b*DDD*NNN;
    const float*  bbase = attn_bias + head*NNN;

    unsigned ksb = (unsigned)__cvta_generic_to_shared(&ksm[0][0])
                 + ((((mi>>1)*8 + mr)*KSTRH) + (mi & 1)*8) * 2;
    unsigned vsb = (unsigned)__cvta_generic_to_shared(&vsm[0][0])
                 + ((mr*VSTRH) + mi*8) * 2;

    int sk_key = t >> 1, sk_c8 = (t & 1) * 8;

#define STAGE(BF, K0) do { \
    cp16(&ksm[BF][sk_key*KSTRH + sk_c8], &kbase[(size_t)((K0) + sk_key)*KDD + sk_c8]); \
    _Pragma("unroll") \
    for (int i2 = 0; i2 < 4; i2++) { \
        int dd = (t + i2*128) >> 3, ch = (t + i2*128) & 7; \
        cp16(&vsm[BF][dd*VSTRH + ch*8], &vbase[(size_t)dd*NNN + (K0) + ch*8]); } \
    if (t < 16) cp16(&bism[BF][t*4], &bbase[(K0) + t*4]); \
} while (0)

    // Q fragments (log2e pre-folded)
    unsigned aQ[4];
    {
        int r0 = q0 + w*16 + g, r1 = r0 + 8;
        const __half* qb = g_qh + (size_t)b*NNN*KDD;
        aQ[0] = *(const unsigned*)&qb[(size_t)r0*KDD + 2*qd];
        aQ[1] = *(const unsigned*)&qb[(size_t)r1*KDD + 2*qd];
        aQ[2] = *(const unsigned*)&qb[(size_t)r0*KDD + 2*qd + 8];
        aQ[3] = *(const unsigned*)&qb[(size_t)r1*KDD + 2*qd + 8];
    }

    // static shifts
    float m0, m1;
    {
        float q2_0 = 0.f, q2_1 = 0.f;
        #pragma unroll
        for (int i = 0; i < 4; i++) {
            float2 f = __half22float2(*(__half2*)&aQ[i]);
            float ss = f.x*f.x + f.y*f.y;
            if (i & 1) q2_1 += ss; else q2_0 += ss;
        }
        q2_0 += __shfl_xor_sync(0xffffffffu, q2_0, 1);
        q2_0 += __shfl_xor_sync(0xffffffffu, q2_0, 2);
        q2_1 += __shfl_xor_sync(0xffffffffu, q2_1, 1);
        q2_1 += __shfl_xor_sync(0xffffffffu, q2_1, 2);
        float kmax2 = __uint_as_float(g_kmaxu[head*BBB + b]);
        float bmax  = g_bmax[head];
        m0 = sqrtf(q2_0 * kmax2) + bmax - 8.f;
        m1 = sqrtf(q2_1 * kmax2) + bmax - 8.f;
    }

#define COMPUTE_S(KB1) do { \
    unsigned kA = ksb + (KB1)*KBYTES; \
    const float* bb = bism[KB1]; \
    _Pragma("unroll") \
    for (int j = 0; j < 4; j++) { \
        float2 bbA = *(const float2*)&bb[(2*j)*8 + 2*qd]; \
        float2 bbB = *(const float2*)&bb[(2*j+1)*8 + 2*qd]; \
        Sv[2*j  ][0] = fmaf(bbA.x, L2E, -m0); \
        Sv[2*j  ][1] = fmaf(bbA.y, L2E, -m0); \
        Sv[2*j  ][2] = fmaf(bbA.x, L2E, -m1); \
        Sv[2*j  ][3] = fmaf(bbA.y, L2E, -m1); \
        Sv[2*j+1][0] = fmaf(bbB.x, L2E, -m0); \
        Sv[2*j+1][1] = fmaf(bbB.y, L2E, -m0); \
        Sv[2*j+1][2] = fmaf(bbB.x, L2E, -m1); \
        Sv[2*j+1][3] = fmaf(bbB.y, L2E, -m1); \
        unsigned r0, r1, r2, r3; \
        ldsm4(r0, r1, r2, r3, kA + j*(16*KSTRH*2)); \
        mma_f16(Sv[2*j  ], aQ, r0, r1); \
        mma_f16(Sv[2*j+1], aQ, r2, r3); \
    } \
} while (0)

    float Oa[8][4];
    #pragma unroll
    for (int nt = 0; nt < 8; nt++)
        #pragma unroll
        for (int j = 0; j < 4; j++) Oa[nt][j] = 0.f;
    float Lacc[4] = {0.f, 0.f, 0.f, 0.f};

    // prologue: stage tiles 0,1; compute S(0)
    STAGE(0, 0);   CP_COMMIT;
    STAGE(1, 64);  CP_COMMIT;
    CP_WAIT1;
    __syncthreads();

    float Sv[8][4];
    COMPUTE_S(0);

    int c0 = 0, c1 = 1, c2 = 2;
    for (int kt = 0; kt < 25; kt++) {
        __syncthreads();                       // all readers of buffer c2 (= kt-1) done
        if (kt + 2 < 25) STAGE(c2, (kt + 2)*64);
        CP_COMMIT;
        CP_WAIT1;                              // group(kt+1) complete

        // ---- P = 2^Sv, pack to fp16 ----
        unsigned Ph[4][4];
        #pragma unroll
        for (int kc = 0; kc < 4; kc++) {
            float pA0 = ex2(Sv[2*kc  ][0]);
            float pA1 = ex2(Sv[2*kc  ][1]);
            float pA2 = ex2(Sv[2*kc  ][2]);
            float pA3 = ex2(Sv[2*kc  ][3]);
            float pB0 = ex2(Sv[2*kc+1][0]);
            float pB1 = ex2(Sv[2*kc+1][1]);
            float pB2 = ex2(Sv[2*kc+1][2]);
            float pB3 = ex2(Sv[2*kc+1][3]);
            Ph[kc][0] = packh2(pA0, pA1);
            Ph[kc][1] = packh2(pA2, pA3);
            Ph[kc][2] = packh2(pB0, pB1);
            Ph[kc][3] = packh2(pB2, pB3);
        }
        // ---- l += P @ ones (row sums on tensor core, no shuffles) ----
        #pragma unroll
        for (int kc = 0; kc < 4; kc++)
            mma_f16(Lacc, Ph[kc], ONE2, ONE2);

        // ---- refill Sv for next tile (independent stream) ----
        if (kt + 1 < 25) COMPUTE_S(c1);

        // ---- O += P V ----
        unsigned vA = vsb + c0*VBYTES;
        #pragma unroll
        for (int nt = 0; nt < 8; nt++) {
            unsigned d0, d1, d2, d3;
            ldsm4(d0, d1, d2, d3, vA + nt*(8*VSTRH*2));
            mma_f16(Oa[nt], Ph[0], d0, d1);
            mma_f16(Oa[nt], Ph[1], d2, d3);
            ldsm4(d0, d1, d2, d3, vA + nt*(8*VSTRH*2) + 64);
            mma_f16(Oa[nt], Ph[2], d0, d1);
            mma_f16(Oa[nt], Ph[3], d2, d3);
        }

        int tmp = c0; c0 = c1; c1 = c2; c2 = tmp;
    }

    // ---- epilogue: l fully reduced in Lacc ----
    float inv0 = 1.f / Lacc[0], inv1 = 1.f / Lacc[2];
    int n0 = q0 + w*16 + g, n1 = n0 + 8;
    #pragma unroll
    for (int nt = 0; nt < 8; nt++) {
        int d = nt*8 + 2*qd;
        float o00 = Oa[nt][0] * inv0, o01 = Oa[nt][1] * inv0;
        float o10 = Oa[nt][2] * inv1, o11 = Oa[nt][3] * inv1;
        *(__half2*)&g_cath[((size_t)b*NNN + n0)*DIMC + head*DDD + d] = __floats2half2_rn(o00, o01);
        *(__half2*)&g_cath[((size_t)b*NNN + n1)*DIMC + head*DDD + d] = __floats2half2_rn(o10, o11);
        g_prev[((size_t)b*HDD + d    )*NNN + n0] = o00;
        g_prev[((size_t)b*HDD + d + 1)*NNN + n0] = o01;
        g_prev[((size_t)b*HDD + d    )*NNN + n1] = o10;
        g_prev[((size_t)b*HDD + d + 1)*NNN + n1] = o11;
    }
#undef STAGE
#undef COMPUTE_S
}

// ---------------- final proj: fp16 MMA ----------------
#define PSTRH 24

__global__ __launch_bounds__(256) void proj_mma(float* __restrict__ out)
{
    __shared__ __align__(16) __half xsm[2][160*PSTRH];
    __shared__ __align__(16) __half wsm[2][64*PSTRH];

    int bi = blockIdx.x;
    int b  = bi / 40;
    int r  = bi % 40;
    int p0 = (r / 4) * 160;
    int o0 = (r % 4) * 64;

    int t    = threadIdx.x;
    int wid  = t >> 5;
    int lane = t & 31;
    int g    = lane >> 2;
    int qd   = lane & 3;
    int wo   = wid & 3;
    int wp   = wid >> 2;

    const __half* xb = g_cath + (size_t)b*NNN*DIMC;

    float Oa[10][4];
    #pragma unroll
    for (int nt = 0; nt < 10; nt++)
        #pragma unroll
        for (int j = 0; j < 4; j++) Oa[nt][j] = 0.f;

    {
        for (int i = t; i < 128; i += 256) {
            int row = i >> 1, c8 = (i & 1) * 8;
            cp16(&wsm[0][row*PSTRH + c8], &g_p_wh[(o0 + row)*DIMC + c8]);
        }
        for (int i = t; i < 320; i += 256) {
            int row = i >> 1, c8 = (i & 1) * 8;
            cp16(&xsm[0][row*PSTRH + c8], &xb[(size_t)(p0 + row)*DIMC + c8]);
        }
        CP_COMMIT;
    }

    for (int s = 0; s < 16; s++) {
        int buf = s & 1;
        if (s + 1 < 16) {
            int cc0 = (s + 1) * 16, nb = buf ^ 1;
            for (int i = t; i < 128; i += 256) {
                int row = i >> 1, c8 = (i & 1) * 8;
                cp16(&wsm[nb][row*PSTRH + c8], &g_p_wh[(o0 + row)*DIMC + cc0 + c8]);
            }
            for (int i = t; i < 320; i += 256) {
                int row = i >> 1, c8 = (i & 1) * 8;
                cp16(&xsm[nb][row*PSTRH + c8], &xb[(size_t)(p0 + row)*DIMC + cc0 + c8]);
            }
        }
        CP_COMMIT;
        CP_WAIT1;
        __syncthreads();

        unsigned a[4];
        a[0] = *(const unsigned*)&wsm[buf][(wo*16 + g    )*PSTRH + 2*qd];
        a[1] = *(const unsigned*)&wsm[buf][(wo*16 + g + 8)*PSTRH + 2*qd];
        a[2] = *(const unsigned*)&wsm[buf][(wo*16 + g    )*PSTRH + 2*qd + 8];
        a[3] = *(const unsigned*)&wsm[buf][(wo*16 + g + 8)*PSTRH + 2*qd + 8];
        #pragma unroll
        for (int nt = 0; nt < 10; nt++) {
            unsigned b0 = *(const unsigned*)&xsm[buf][(wp*80 + nt*8 + g)*PSTRH + 2*qd];
            unsigned b1 = *(const unsigned*)&xsm[buf][(wp*80 + nt*8 + g)*PSTRH + 2*qd + 8];
            mma_f16(Oa[nt], a, b0, b1);
        }
        __syncthreads();
    }

    int orow0 = o0 + wo*16 + g, orow1 = orow0 + 8;
    float bb0 = g_p_bf[orow0], bb1 = g_p_bf[orow1];
    #pragma unroll
    for (int nt = 0; nt < 10; nt++) {
        int n = p0 + wp*80 + nt*8 + 2*qd;
        float v00 = fmaxf(Oa[nt][0] + bb0, 0.f);
        float v01 = fmaxf(Oa[nt][1] + bb0, 0.f);
        float v10 = fmaxf(Oa[nt][2] + bb1, 0.f);
        float v11 = fmaxf(Oa[nt][3] + bb1, 0.f);
        *(float2*)&out[((size_t)b*DIMC + orow0)*NNN + n] = make_float2(v00, v01);
        *(float2*)&out[((size_t)b*DIMC + orow1)*NNN + n] = make_float2(v10, v11);
    }
}

// ---------------- launch ----------------
extern "C" void kernel_launch(void* const* d_in, const int* in_sizes, int n_in,
                              void* d_out, int out_size)
{
    const float* x    = (const float*)d_in[0];
    const float* dw_w = (const float*)d_in[1];
    const float* dw_g = (const float*)d_in[2];
    const float* dw_b = (const float*)d_in[3];
    const float* dw_m = (const float*)d_in[4];
    const float* dw_v = (const float*)d_in[5];
    const float* q_w  = (const float*)d_in[6];
    const float* q_g  = (const float*)d_in[7];
    const float* q_b  = (const float*)d_in[8];
    const float* q_m  = (const float*)d_in[9];
    const float* q_v  = (const float*)d_in[10];
    const float* k_w  = (const float*)d_in[11];
    const float* k_g  = (const float*)d_in[12];
    const float* k_b  = (const float*)d_in[13];
    const float* k_m  = (const float*)d_in[14];
    const float* k_v  = (const float*)d_in[15];
    const float* v_w  = (const float*)d_in[16];
    const float* v_g  = (const float*)d_in[17];
    const float* v_b  = (const float*)d_in[18];
    const float* v_m  = (const float*)d_in[19];
    const float* v_v  = (const float*)d_in[20];
    const float* p_w  = (const float*)d_in[21];
    const float* p_g  = (const float*)d_in[22];
    const float* p_b  = (const float*)d_in[23];
    const float* p_m  = (const float*)d_in[24];
    const float* p_v  = (const float*)d_in[25];
    const float* attn_bias = (const float*)d_in[26];

    prep_fold<<<128, 256>>>(dw_w, dw_g, dw_b, dw_m, dw_v,
                            q_w, q_g, q_b, q_m, q_v,
                            k_w, k_g, k_b, k_m, k_v,
                            v_w, v_g, v_b, v_m, v_v,
                            p_w, p_g, p_b, p_m, p_v, attn_bias);

    dwconv_all<<<(BBB*DIMC*400)/256, 256>>>(x);

    for (int i = 0; i < NHH; i++) {
        qkv_mma<<<BBB*25, 256>>>(i, i > 0 ? 1 : 0);
        attn_mma<<<BBB*25, 128>>>(attn_bias, i);
    }

    proj_mma<<<640, 256>>>((float*)d_out);
}

// round 15
// speedup vs baseline: 1.0944x; 1.0944x over previous
#include <cuda_runtime.h>
#include <cuda_fp16.h>
#include <math.h>

#define NHH   4
#define HDD   64
#define KDD   16
#define DDD   64
#define NNN   1600
#define BBB   16
#define HIMG  40
#define WIMG  40
#define DIMC  256
#define EPSB  1e-5f
#define SCALEQ 0.25f
#define L2E   1.4426950408889634f

// ---------------- device scratch ----------------
__device__ float    g_conv[BBB*DIMC*NNN];
__device__ __half   g_qh [BBB*NNN*KDD];
__device__ __half   g_kh [BBB*NNN*KDD];
__device__ __half   g_vT [BBB*DDD*NNN];
__device__ float    g_prev[BBB*HDD*NNN];
__device__ __half   g_cath[BBB*NNN*DIMC];
__device__ float    g_dw_wf[NHH*HDD*25];
__device__ float    g_dw_bf[NHH*HDD];
__device__ __half   g_qkv_wh[NHH*96*HDD];
__device__ float    g_qkv_bf[NHH*96];
__device__ __half   g_p_wh[DIMC*DIMC];
__device__ float    g_p_bf[DIMC];
__device__ unsigned g_kmaxu[NHH*BBB];
__device__ float    g_bmax[NHH];

// ---------------- helpers ----------------
__device__ __forceinline__ unsigned packh2(float a, float b) {
    __half2 h = __floats2half2_rn(a, b);
    return *(unsigned*)&h;
}
__device__ __forceinline__ unsigned h2ex2(unsigned x) {
    unsigned r; asm("ex2.approx.f16x2 %0, %1;" : "=r"(r) : "r"(x)); return r;
}
__device__ __forceinline__ void mma_f16(float c[4], const unsigned a[4],
                                        unsigned b0, unsigned b1) {
    asm volatile("mma.sync.aligned.m16n8k16.row.col.f32.f16.f16.f32 "
        "{%0,%1,%2,%3}, {%4,%5,%6,%7}, {%8,%9}, {%0,%1,%2,%3};"
        : "+f"(c[0]), "+f"(c[1]), "+f"(c[2]), "+f"(c[3])
        : "r"(a[0]), "r"(a[1]), "r"(a[2]), "r"(a[3]), "r"(b0), "r"(b1));
}
__device__ __forceinline__ void ldsm4(unsigned& r0, unsigned& r1, unsigned& r2, unsigned& r3,
                                      unsigned addr) {
    asm volatile("ldmatrix.sync.aligned.m8n8.x4.shared.b16 {%0,%1,%2,%3}, [%4];"
        : "=r"(r0), "=r"(r1), "=r"(r2), "=r"(r3) : "r"(addr));
}
__device__ __forceinline__ void cp16(void* dst, const void* src) {
    unsigned d = (unsigned)__cvta_generic_to_shared(dst);
    asm volatile("cp.async.cg.shared.global [%0], [%1], 16;" :: "r"(d), "l"(src));
}
#define CP_COMMIT asm volatile("cp.async.commit_group;" ::: "memory")
#define CP_WAIT1  asm volatile("cp.async.wait_group 1;"  ::: "memory")
#define CP_WAIT0  asm volatile("cp.async.wait_group 0;"  ::: "memory")

// ---------------- fold BN into weights + bias-max + kmax reset ----------------
__global__ void prep_fold(
    const float* dw_w, const float* dw_g, const float* dw_b, const float* dw_m, const float* dw_v,
    const float* q_w,  const float* q_g,  const float* q_b,  const float* q_m,  const float* q_v,
    const float* k_w,  const float* k_g,  const float* k_b,  const float* k_m,  const float* k_v,
    const float* v_w,  const float* v_g,  const float* v_b,  const float* v_m,  const float* v_v,
    const float* p_w,  const float* p_g,  const float* p_b,  const float* p_m,  const float* p_v,
    const float* attn_bias)
{
    int t = blockIdx.x * blockDim.x + threadIdx.x;
    int stride = gridDim.x * blockDim.x;

    for (int idx = t; idx < NHH*HDD*25; idx += stride) {
        int ch = idx / 25;
        float s = dw_g[ch] * rsqrtf(dw_v[ch] + EPSB);
        g_dw_wf[idx] = dw_w[idx] * s;
    }
    for (int ch = t; ch < NHH*HDD; ch += stride) {
        float s = dw_g[ch] * rsqrtf(dw_v[ch] + EPSB);
        g_dw_bf[ch] = dw_b[ch] - s * dw_m[ch];
    }
    for (int idx = t; idx < NHH*96*HDD; idx += stride) {
        int r = idx / HDD, c = idx % HDD;
        int i = r / 96, oc = r % 96;
        float s; const float* w;
        if (oc < 16) {
            int j = i*KDD + oc;
            s = q_g[j] * rsqrtf(q_v[j] + EPSB) * (SCALEQ * L2E);
            w = q_w + (size_t)j * HDD;
        } else if (oc < 32) {
            int j = i*KDD + (oc - 16);
            s = k_g[j] * rsqrtf(k_v[j] + EPSB);
            w = k_w + (size_t)j * HDD;
        } else {
            int j = i*DDD + (oc - 32);
            s = v_g[j] * rsqrtf(v_v[j] + EPSB);
            w = v_w + (size_t)j * HDD;
        }
        g_qkv_wh[idx] = __float2half_rn(w[c] * s);
    }
    for (int r = t; r < NHH*96; r += stride) {
        int i = r / 96, oc = r % 96;
        float s, bias;
        if (oc < 16) {
            int j = i*KDD + oc;
            s = q_g[j] * rsqrtf(q_v[j] + EPSB);
            bias = (q_b[j] - s * q_m[j]) * (SCALEQ * L2E);
        } else if (oc < 32) {
            int j = i*KDD + (oc - 16);
            s = k_g[j] * rsqrtf(k_v[j] + EPSB);
            bias = k_b[j] - s * k_m[j];
        } else {
            int j = i*DDD + (oc - 32);
            s = v_g[j] * rsqrtf(v_v[j] + EPSB);
            bias = v_b[j] - s * v_m[j];
        }
        g_qkv_bf[r] = bias;
    }
    for (int idx = t; idx < DIMC*DIMC; idx += stride) {
        int o = idx / DIMC;
        float s = p_g[o] * rsqrtf(p_v[o] + EPSB);
        g_p_wh[idx] = __float2half_rn(p_w[idx] * s);
    }
    for (int o = t; o < DIMC; o += stride) {
        float s = p_g[o] * rsqrtf(p_v[o] + EPSB);
        g_p_bf[o] = p_b[o] - s * p_m[o];
    }

    if (blockIdx.x == 0) {
        int tt = threadIdx.x;
        if (tt < NHH*BBB) g_kmaxu[tt] = 0u;
        int wrp = tt >> 5, ln = tt & 31;
        if (wrp < NHH) {
            float mx = -1e30f;
            for (int n = ln; n < NNN; n += 32)
                mx = fmaxf(mx, attn_bias[wrp*NNN + n]);
            #pragma unroll
            for (int msk = 16; msk; msk >>= 1)
                mx = fmaxf(mx, __shfl_xor_sync(0xffffffffu, mx, msk));
            if (ln == 0) g_bmax[wrp] = mx * L2E;
        }
    }
}

// ---------------- depthwise 5x5 conv, 4 outputs/thread ----------------
__global__ __launch_bounds__(256) void dwconv_all(const float* __restrict__ x)
{
    int idx = blockIdx.x * 256 + threadIdx.x;
    int n4 = idx % 400;
    int c  = (idx / 400) % DIMC;
    int b  = idx / (400 * DIMC);
    int h  = n4 / 10, w0 = (n4 % 10) * 4;

    const float* xin = x + ((size_t)b * DIMC + c) * NNN;
    const float* wf  = g_dw_wf + c * 25;
    float bias = g_dw_bf[c];
    float a0 = bias, a1 = bias, a2 = bias, a3 = bias;

    #pragma unroll
    for (int dy = 0; dy < 5; dy++) {
        int hh = h + dy - 2;
        if ((unsigned)hh >= (unsigned)HIMG) continue;
        const float* row = xin + hh*WIMG;
        float v[8];
        #pragma unroll
        for (int j = 0; j < 8; j++) {
            int ww = w0 - 2 + j;
            v[j] = ((unsigned)ww < (unsigned)WIMG) ? row[ww] : 0.f;
        }
        #pragma unroll
        for (int dx = 0; dx < 5; dx++) {
            float wt = wf[dy*5 + dx];
            a0 += wt*v[dx];   a1 += wt*v[dx+1];
            a2 += wt*v[dx+2]; a3 += wt*v[dx+3];
        }
    }
    *(float4*)&g_conv[((size_t)b*DIMC + c)*NNN + h*WIMG + w0] = make_float4(a0, a1, a2, a3);
}

// ---------------- QKV projection via fp16 MMA (+ fused prev add + k-norm max) ----------------
__global__ __launch_bounds__(256) void qkv_mma(int head, int addprev)
{
    __shared__ __align__(16) __half wsh[96*72];
    __shared__ __align__(16) __half xsh[64*72];

    int b  = blockIdx.x / 25;
    int p0 = (blockIdx.x % 25) * 64;
    int t  = threadIdx.x;
    int wp   = t >> 5;
    int lane = t & 31;
    int g    = lane >> 2;
    int qd   = lane & 3;

    for (int i = t; i < 768; i += 256) {
        int row = i >> 3, c8 = (i & 7) * 8;
        cp16(&wsh[row*72 + c8], &g_qkv_wh[(size_t)head*96*64 + row*64 + c8]);
    }
    CP_COMMIT;

    {
        int c  = t >> 2;
        int i4 = t & 3;
        int cX = c ^ (i4 << 3);
        const float* cb = g_conv + ((size_t)b*DIMC + head*HDD + c)*NNN + p0 + i4*16;
        const float* pb = g_prev + ((size_t)b*HDD + c)*NNN + p0 + i4*16;
        #pragma unroll
        for (int j4 = 0; j4 < 4; j4++) {
            float4 f = *(const float4*)&cb[j4*4];
            if (addprev) {
                float4 pv = *(const float4*)&pb[j4*4];
                f.x += pv.x; f.y += pv.y; f.z += pv.z; f.w += pv.w;
            }
            int pbase = i4*16 + j4*4;
            xsh[(pbase + 0)*72 + cX] = __float2half_rn(f.x);
            xsh[(pbase + 1)*72 + cX] = __float2half_rn(f.y);
            xsh[(pbase + 2)*72 + cX] = __float2half_rn(f.z);
            xsh[(pbase + 3)*72 + cX] = __float2half_rn(f.w);
        }
    }
    CP_WAIT0;
    __syncthreads();

    int n0 = wp * 8;
    int cXor = ((wp >> 1) & 3) << 3;
    float acc[6][4];
    #pragma unroll
    for (int mt = 0; mt < 6; mt++)
        #pragma unroll
        for (int j = 0; j < 4; j++) acc[mt][j] = 0.f;

    #pragma unroll
    for (int ks = 0; ks < 4; ks++) {
        unsigned b0 = *(const unsigned*)&xsh[(n0 + g)*72 + ((ks*16 + 2*qd    ) ^ cXor)];
        unsigned b1 = *(const unsigned*)&xsh[(n0 + g)*72 + ((ks*16 + 2*qd + 8) ^ cXor)];
        #pragma unroll
        for (int mt = 0; mt < 6; mt++) {
            unsigned a[4];
            a[0] = *(const unsigned*)&wsh[(mt*16 + g    )*72 + ks*16 + 2*qd];
            a[1] = *(const unsigned*)&wsh[(mt*16 + g + 8)*72 + ks*16 + 2*qd];
            a[2] = *(const unsigned*)&wsh[(mt*16 + g    )*72 + ks*16 + 2*qd + 8];
            a[3] = *(const unsigned*)&wsh[(mt*16 + g + 8)*72 + ks*16 + 2*qd + 8];
            mma_f16(acc[mt], a, b0, b1);
        }
    }

    float kn0 = 0.f, kn1 = 0.f;
    int n = p0 + n0 + 2*qd;
    #pragma unroll
    for (int mt = 0; mt < 6; mt++) {
        int oc0 = mt*16 + g, oc1 = oc0 + 8;
        float bb0 = g_qkv_bf[head*96 + oc0];
        float bb1 = g_qkv_bf[head*96 + oc1];
        float v00 = acc[mt][0] + bb0, v01 = acc[mt][1] + bb0;
        float v10 = acc[mt][2] + bb1, v11 = acc[mt][3] + bb1;
        if (mt == 0) {
            g_qh[((size_t)b*NNN + n    )*KDD + oc0] = __float2half_rn(v00);
            g_qh[((size_t)b*NNN + n + 1)*KDD + oc0] = __float2half_rn(v01);
            g_qh[((size_t)b*NNN + n    )*KDD + oc1] = __float2half_rn(v10);
            g_qh[((size_t)b*NNN + n + 1)*KDD + oc1] = __float2half_rn(v11);
        } else if (mt == 1) {
            int k0 = oc0 - 16, k1 = oc1 - 16;
            g_kh[((size_t)b*NNN + n    )*KDD + k0] = __float2half_rn(v00);
            g_kh[((size_t)b*NNN + n + 1)*KDD + k0] = __float2half_rn(v01);
            g_kh[((size_t)b*NNN + n    )*KDD + k1] = __float2half_rn(v10);
            g_kh[((size_t)b*NNN + n + 1)*KDD + k1] = __float2half_rn(v11);
            kn0 = v00*v00 + v10*v10;
            kn1 = v01*v01 + v11*v11;
        } else {
            int d0 = oc0 - 32, d1 = oc1 - 32;
            *(__half2*)&g_vT[((size_t)b*DDD + d0)*NNN + n] = __floats2half2_rn(v00, v01);
            *(__half2*)&g_vT[((size_t)b*DDD + d1)*NNN + n] = __floats2half2_rn(v10, v11);
        }
    }

    #pragma unroll
    for (int msk = 4; msk <= 16; msk <<= 1) {
        kn0 += __shfl_xor_sync(0xffffffffu, kn0, msk);
        kn1 += __shfl_xor_sync(0xffffffffu, kn1, msk);
    }
    float kmx = fmaxf(kn0, kn1);
    kmx = fmaxf(kmx, __shfl_xor_sync(0xffffffffu, kmx, 1));
    kmx = fmaxf(kmx, __shfl_xor_sync(0xffffffffu, kmx, 2));
    if (lane == 0)
        atomicMax(&g_kmaxu[head*BBB + b], __float_as_uint(kmx));
}

// ---------------- fp16 MMA flash attention: R9 pipeline + f16x2 exp + l-via-MMA ----------------
#define KSTRH 24
#define VSTRH 72
#define KBYTES (64*KSTRH*2)    // 3072
#define VBYTES (64*VSTRH*2)    // 9216
#define ONE2  0x3C003C00u

__global__ __launch_bounds__(128) void attn_mma(const float* __restrict__ attn_bias, int head)
{
    __shared__ __align__(16) __half ksm[3][64*KSTRH];    //  9216 B
    __shared__ __align__(16) __half vsm[4][64*VSTRH];    // 36864 B
    __shared__ __align__(16) float  bism[3][64];         //   768 B

    int b  = blockIdx.x / 25;
    int q0 = (blockIdx.x % 25) * 64;
    int t    = threadIdx.x;
    int w    = t >> 5;
    int lane = t & 31;
    int g    = lane >> 2;
    int qd   = lane & 3;
    int mi   = lane >> 3;
    int mr   = lane & 7;

    const __half* kbase = g_kh + (size_t)b*NNN*KDD;
    const __half* vbase = g_vT + (size_t)b*DDD*NNN;
    const float*  bbase = attn_bias + head*NNN;

    unsigned ksb = (unsigned)__cvta_generic_to_shared(&ksm[0][0])
                 + ((((mi>>1)*8 + mr)*KSTRH) + (mi & 1)*8) * 2;
    unsigned vsb = (unsigned)__cvta_generic_to_shared(&vsm[0][0])
                 + ((mr*VSTRH) + mi*8) * 2;

    int sk_key = t >> 1, sk_c8 = (t & 1) * 8;

#define STAGE(KB, VB, K0) do { \
    cp16(&ksm[KB][sk_key*KSTRH + sk_c8], &kbase[(size_t)((K0) + sk_key)*KDD + sk_c8]); \
    _Pragma("unroll") \
    for (int i2 = 0; i2 < 4; i2++) { \
        int dd = (t + i2*128) >> 3, ch = (t + i2*128) & 7; \
        cp16(&vsm[VB][dd*VSTRH + ch*8], &vbase[(size_t)dd*NNN + (K0) + ch*8]); } \
    if (t < 16) cp16(&bism[KB][t*4], &bbase[(K0) + t*4]); \
} while (0)

    // Q fragments (log2e pre-folded)
    unsigned aQ[4];
    {
        int r0 = q0 + w*16 + g, r1 = r0 + 8;
        const __half* qb = g_qh + (size_t)b*NNN*KDD;
        aQ[0] = *(const unsigned*)&qb[(size_t)r0*KDD + 2*qd];
        aQ[1] = *(const unsigned*)&qb[(size_t)r1*KDD + 2*qd];
        aQ[2] = *(const unsigned*)&qb[(size_t)r0*KDD + 2*qd + 8];
        aQ[3] = *(const unsigned*)&qb[(size_t)r1*KDD + 2*qd + 8];
    }

    // static shifts
    float m0, m1;
    {
        float q2_0 = 0.f, q2_1 = 0.f;
        #pragma unroll
        for (int i = 0; i < 4; i++) {
            float2 f = __half22float2(*(__half2*)&aQ[i]);
            float ss = f.x*f.x + f.y*f.y;
            if (i & 1) q2_1 += ss; else q2_0 += ss;
        }
        q2_0 += __shfl_xor_sync(0xffffffffu, q2_0, 1);
        q2_0 += __shfl_xor_sync(0xffffffffu, q2_0, 2);
        q2_1 += __shfl_xor_sync(0xffffffffu, q2_1, 1);
        q2_1 += __shfl_xor_sync(0xffffffffu, q2_1, 2);
        float kmax2 = __uint_as_float(g_kmaxu[head*BBB + b]);
        float bmax  = g_bmax[head];
        m0 = sqrtf(q2_0 * kmax2) + bmax - 8.f;
        m1 = sqrtf(q2_1 * kmax2) + bmax - 8.f;
    }

#define COMPUTE_S(SV, KB1) do { \
    unsigned kA = ksb + (KB1)*KBYTES; \
    const float* bb = bism[KB1]; \
    _Pragma("unroll") \
    for (int j = 0; j < 4; j++) { \
        float2 bbA = *(const float2*)&bb[(2*j)*8 + 2*qd]; \
        float2 bbB = *(const float2*)&bb[(2*j+1)*8 + 2*qd]; \
        SV[2*j  ][0] = fmaf(bbA.x, L2E, -m0); \
        SV[2*j  ][1] = fmaf(bbA.y, L2E, -m0); \
        SV[2*j  ][2] = fmaf(bbA.x, L2E, -m1); \
        SV[2*j  ][3] = fmaf(bbA.y, L2E, -m1); \
        SV[2*j+1][0] = fmaf(bbB.x, L2E, -m0); \
        SV[2*j+1][1] = fmaf(bbB.y, L2E, -m0); \
        SV[2*j+1][2] = fmaf(bbB.x, L2E, -m1); \
        SV[2*j+1][3] = fmaf(bbB.y, L2E, -m1); \
        unsigned r0, r1, r2, r3; \
        ldsm4(r0, r1, r2, r3, kA + j*(16*KSTRH*2)); \
        mma_f16(SV[2*j  ], aQ, r0, r1); \
        mma_f16(SV[2*j+1], aQ, r2, r3); \
    } \
} while (0)

// pack S to half2 first, then one ex2.approx.f16x2 per pair; l via MMA-with-ones
#define SOFTPV(SV, VB) do { \
    unsigned Ph[4][4]; \
    _Pragma("unroll") \
    for (int kc = 0; kc < 4; kc++) { \
        Ph[kc][0] = h2ex2(packh2(SV[2*kc  ][0], SV[2*kc  ][1])); \
        Ph[kc][1] = h2ex2(packh2(SV[2*kc  ][2], SV[2*kc  ][3])); \
        Ph[kc][2] = h2ex2(packh2(SV[2*kc+1][0], SV[2*kc+1][1])); \
        Ph[kc][3] = h2ex2(packh2(SV[2*kc+1][2], SV[2*kc+1][3])); \
    } \
    _Pragma("unroll") \
    for (int kc = 0; kc < 4; kc++) \
        mma_f16(Lacc, Ph[kc], ONE2, ONE2); \
    unsigned vA = vsb + (VB)*VBYTES; \
    _Pragma("unroll") \
    for (int nt = 0; nt < 8; nt++) { \
        unsigned d0, d1, d2, d3; \
        ldsm4(d0, d1, d2, d3, vA + nt*(8*VSTRH*2)); \
        mma_f16(Oa[nt], Ph[0], d0, d1); \
        mma_f16(Oa[nt], Ph[1], d2, d3); \
        ldsm4(d0, d1, d2, d3, vA + nt*(8*VSTRH*2) + 64); \
        mma_f16(Oa[nt], Ph[2], d0, d1); \
        mma_f16(Oa[nt], Ph[3], d2, d3); \
    } \
} while (0)

#define TILE(KT, CUR, NXT) do { \
    if ((KT) + 2 < 25) STAGE(kstg3, ((KT)+2) & 3, ((KT)+2)*64); \
    CP_COMMIT; \
    CP_WAIT1; \
    __syncthreads(); \
    if ((KT) + 1 < 25) COMPUTE_S(NXT, krd3); \
    SOFTPV(CUR, (KT) & 3); \
    kstg3 = (kstg3 == 2) ? 0 : kstg3 + 1; \
    krd3  = (krd3  == 2) ? 0 : krd3  + 1; \
} while (0)

    float Oa[8][4];
    #pragma unroll
    for (int nt = 0; nt < 8; nt++)
        #pragma unroll
        for (int j = 0; j < 4; j++) Oa[nt][j] = 0.f;
    float Lacc[4] = {0.f, 0.f, 0.f, 0.f};

    // prologue: stage tiles 0,1; compute S(0)
    STAGE(0, 0, 0);   CP_COMMIT;
    STAGE(1, 1, 64);  CP_COMMIT;
    CP_WAIT1;
    __syncthreads();

    float SvA[8][4], SvB[8][4];
    COMPUTE_S(SvA, 0);

    int kstg3 = 2, krd3 = 1;
    for (int kt = 0; kt < 24; kt += 2) {
        TILE(kt,     SvA, SvB);
        TILE(kt + 1, SvB, SvA);
    }
    TILE(24, SvA, SvB);

    // ---- epilogue: l fully reduced in Lacc (no shuffles) ----
    float inv0 = 1.f / Lacc[0], inv1 = 1.f / Lacc[2];
    int n0 = q0 + w*16 + g, n1 = n0 + 8;
    #pragma unroll
    for (int nt = 0; nt < 8; nt++) {
        int d = nt*8 + 2*qd;
        float o00 = Oa[nt][0] * inv0, o01 = Oa[nt][1] * inv0;
        float o10 = Oa[nt][2] * inv1, o11 = Oa[nt][3] * inv1;
        *(__half2*)&g_cath[((size_t)b*NNN + n0)*DIMC + head*DDD + d] = __floats2half2_rn(o00, o01);
        *(__half2*)&g_cath[((size_t)b*NNN + n1)*DIMC + head*DDD + d] = __floats2half2_rn(o10, o11);
        g_prev[((size_t)b*HDD + d    )*NNN + n0] = o00;
        g_prev[((size_t)b*HDD + d + 1)*NNN + n0] = o01;
        g_prev[((size_t)b*HDD + d    )*NNN + n1] = o10;
        g_prev[((size_t)b*HDD + d + 1)*NNN + n1] = o11;
    }
#undef STAGE
#undef COMPUTE_S
#undef SOFTPV
#undef TILE
}

// ---------------- final proj: fp16 MMA ----------------
#define PSTRH 24

__global__ __launch_bounds__(256) void proj_mma(float* __restrict__ out)
{
    __shared__ __align__(16) __half xsm[2][160*PSTRH];
    __shared__ __align__(16) __half wsm[2][64*PSTRH];

    int bi = blockIdx.x;
    int b  = bi / 40;
    int r  = bi % 40;
    int p0 = (r / 4) * 160;
    int o0 = (r % 4) * 64;

    int t    = threadIdx.x;
    int wid  = t >> 5;
    int lane = t & 31;
    int g    = lane >> 2;
    int qd   = lane & 3;
    int wo   = wid & 3;
    int wp   = wid >> 2;

    const __half* xb = g_cath + (size_t)b*NNN*DIMC;

    float Oa[10][4];
    #pragma unroll
    for (int nt = 0; nt < 10; nt++)
        #pragma unroll
        for (int j = 0; j < 4; j++) Oa[nt][j] = 0.f;

    {
        for (int i = t; i < 128; i += 256) {
            int row = i >> 1, c8 = (i & 1) * 8;
            cp16(&wsm[0][row*PSTRH + c8], &g_p_wh[(o0 + row)*DIMC + c8]);
        }
        for (int i = t; i < 320; i += 256) {
            int row = i >> 1, c8 = (i & 1) * 8;
            cp16(&xsm[0][row*PSTRH + c8], &xb[(size_t)(p0 + row)*DIMC + c8]);
        }
        CP_COMMIT;
    }

    for (int s = 0; s < 16; s++) {
        int buf = s & 1;
        if (s + 1 < 16) {
            int cc0 = (s + 1) * 16, nb = buf ^ 1;
            for (int i = t; i < 128; i += 256) {
                int row = i >> 1, c8 = (i & 1) * 8;
                cp16(&wsm[nb][row*PSTRH + c8], &g_p_wh[(o0 + row)*DIMC + cc0 + c8]);
            }
            for (int i = t; i < 320; i += 256) {
                int row = i >> 1, c8 = (i & 1) * 8;
                cp16(&xsm[nb][row*PSTRH + c8], &xb[(size_t)(p0 + row)*DIMC + cc0 + c8]);
            }
        }
        CP_COMMIT;
        CP_WAIT1;
        __syncthreads();

        unsigned a[4];
        a[0] = *(const unsigned*)&wsm[buf][(wo*16 + g    )*PSTRH + 2*qd];
        a[1] = *(const unsigned*)&wsm[buf][(wo*16 + g + 8)*PSTRH + 2*qd];
        a[2] = *(const unsigned*)&wsm[buf][(wo*16 + g    )*PSTRH + 2*qd + 8];
        a[3] = *(const unsigned*)&wsm[buf][(wo*16 + g + 8)*PSTRH + 2*qd + 8];
        #pragma unroll
        for (int nt = 0; nt < 10; nt++) {
            unsigned b0 = *(const unsigned*)&xsm[buf][(wp*80 + nt*8 + g)*PSTRH + 2*qd];
            unsigned b1 = *(const unsigned*)&xsm[buf][(wp*80 + nt*8 + g)*PSTRH + 2*qd + 8];
            mma_f16(Oa[nt], a, b0, b1);
        }
        __syncthreads();
    }

    int orow0 = o0 + wo*16 + g, orow1 = orow0 + 8;
    float bb0 = g_p_bf[orow0], bb1 = g_p_bf[orow1];
    #pragma unroll
    for (int nt = 0; nt < 10; nt++) {
        int n = p0 + wp*80 + nt*8 + 2*qd;
        float v00 = fmaxf(Oa[nt][0] + bb0, 0.f);
        float v01 = fmaxf(Oa[nt][1] + bb0, 0.f);
        float v10 = fmaxf(Oa[nt][2] + bb1, 0.f);
        float v11 = fmaxf(Oa[nt][3] + bb1, 0.f);
        *(float2*)&out[((size_t)b*DIMC + orow0)*NNN + n] = make_float2(v00, v01);
        *(float2*)&out[((size_t)b*DIMC + orow1)*NNN + n] = make_float2(v10, v11);
    }
}

// ---------------- launch ----------------
extern "C" void kernel_launch(void* const* d_in, const int* in_sizes, int n_in,
                              void* d_out, int out_size)
{
    const float* x    = (const float*)d_in[0];
    const float* dw_w = (const float*)d_in[1];
    const float* dw_g = (const float*)d_in[2];
    const float* dw_b = (const float*)d_in[3];
    const float* dw_m = (const float*)d_in[4];
    const float* dw_v = (const float*)d_in[5];
    const float* q_w  = (const float*)d_in[6];
    const float* q_g  = (const float*)d_in[7];
    const float* q_b  = (const float*)d_in[8];
    const float* q_m  = (const float*)d_in[9];
    const float* q_v  = (const float*)d_in[10];
    const float* k_w  = (const float*)d_in[11];
    const float* k_g  = (const float*)d_in[12];
    const float* k_b  = (const float*)d_in[13];
    const float* k_m  = (const float*)d_in[14];
    const float* k_v  = (const float*)d_in[15];
    const float* v_w  = (const float*)d_in[16];
    const float* v_g  = (const float*)d_in[17];
    const float* v_b  = (const float*)d_in[18];
    const float* v_m  = (const float*)d_in[19];
    const float* v_v  = (const float*)d_in[20];
    const float* p_w  = (const float*)d_in[21];
    const float* p_g  = (const float*)d_in[22];
    const float* p_b  = (const float*)d_in[23];
    const float* p_m  = (const float*)d_in[24];
    const float* p_v  = (const float*)d_in[25];
    const float* attn_bias = (const float*)d_in[26];

    prep_fold<<<128, 256>>>(dw_w, dw_g, dw_b, dw_m, dw_v,
                            q_w, q_g, q_b, q_m, q_v,
                            k_w, k_g, k_b, k_m, k_v,
                            v_w, v_g, v_b, v_m, v_v,
                            p_w, p_g, p_b, p_m, p_v, attn_bias);

    dwconv_all<<<(BBB*DIMC*400)/256, 256>>>(x);

    for (int i = 0; i < NHH; i++) {
        qkv_mma<<<BBB*25, 256>>>(i, i > 0 ? 1 : 0);
        attn_mma<<<BBB*25, 128>>>(attn_bias, i);
    }

    proj_mma<<<640, 256>>>((float*)d_out);
}